// round 1
// baseline (speedup 1.0000x reference)
#include <cuda_runtime.h>
#include <cuda_bf16.h>
#include <cstddef>

// Problem constants
#define BATCH 4
#define NSEQ 2048
#define DIM 512
#define NHEAD 8
#define DHEAD 128
#define INNER 1024          // NHEAD*DHEAD
#define MROWS (BATCH*NSEQ)  // 8192

// Gaussian window half-width: sigma<=2.5 -> exp(-32^2/(2*6.25)) ~ 1e-36, safely negligible
#define WIN 32
#define TN 64               // n-rows per smoothing block

// Scratch (allocation-free rule: __device__ globals)
__device__ float g_y[MROWS * INNER];   // x @ Wg
__device__ float g_s[MROWS * INNER];   // smoothed

typedef unsigned long long ull;

__device__ __forceinline__ ull pack_dup(float a) {
    ull r; asm("mov.b64 %0, {%1, %1};" : "=l"(r) : "f"(a)); return r;
}
__device__ __forceinline__ void ffma2(ull& d, ull a, ull b) {
    asm("fma.rn.f32x2 %0, %1, %2, %0;" : "+l"(d) : "l"(a), "l"(b));
}
__device__ __forceinline__ void unpack2(ull v, float& lo, float& hi) {
    asm("mov.b64 {%0, %1}, %2;" : "=f"(lo), "=f"(hi) : "l"(v));
}

// ---------------------------------------------------------------------------
// 128x128 tiled fp32 GEMM, C = A[M,K] * B[K,N], row-major, using packed f32x2 FMA.
// 256 threads, 8x8 microtile per thread, K-tile = 16, reg-prefetch of next tile.
// Requires M%128==0, N%128==0, K%16==0 (true for all calls here).
// ---------------------------------------------------------------------------
__global__ __launch_bounds__(256, 2)
void gemm128_f32x2(const float* __restrict__ A, const float* __restrict__ B,
                   float* __restrict__ C, int M, int N, int K) {
    __shared__ float As[16][132];   // transposed A tile, padded to cut STS conflicts
    __shared__ float Bs[16][128];

    const int tid = threadIdx.x;
    const int tx = tid & 15;
    const int ty = tid >> 4;
    const int row0 = blockIdx.y << 7;
    const int col0 = blockIdx.x << 7;

    // A tile load mapping: 128 rows x 16 k as 512 float4; thread does idx=tid (rows 0..63)
    // and idx=tid+256 (rows 64..127)
    const int ar0 = tid >> 2;            // 0..63
    const int akc = (tid & 3) << 2;      // k chunk 0,4,8,12
    // B tile load mapping: 16 k x 128 cols as 512 float4
    const int bk0 = tid >> 5;            // 0..7
    const int bjc = (tid & 31) << 2;     // col chunk

    ull acc[8][4];
#pragma unroll
    for (int i = 0; i < 8; i++)
#pragma unroll
        for (int j = 0; j < 4; j++) acc[i][j] = 0ULL;

    const int ktiles = K >> 4;

    float4 ra0, ra1, rb0, rb1;
    {
        const float* Ap = A + (size_t)row0 * K;
        ra0 = *(const float4*)(Ap + (size_t)ar0 * K + akc);
        ra1 = *(const float4*)(Ap + (size_t)(ar0 + 64) * K + akc);
        const float* Bp = B + col0;
        rb0 = *(const float4*)(Bp + (size_t)bk0 * N + bjc);
        rb1 = *(const float4*)(Bp + (size_t)(bk0 + 8) * N + bjc);
    }

    for (int kt = 0; kt < ktiles; kt++) {
        // scatter A (transposed) and store B
        As[akc + 0][ar0] = ra0.x; As[akc + 1][ar0] = ra0.y;
        As[akc + 2][ar0] = ra0.z; As[akc + 3][ar0] = ra0.w;
        As[akc + 0][ar0 + 64] = ra1.x; As[akc + 1][ar0 + 64] = ra1.y;
        As[akc + 2][ar0 + 64] = ra1.z; As[akc + 3][ar0 + 64] = ra1.w;
        *(float4*)&Bs[bk0][bjc]     = rb0;
        *(float4*)&Bs[bk0 + 8][bjc] = rb1;
        __syncthreads();

        if (kt + 1 < ktiles) {
            const int k0 = (kt + 1) << 4;
            const float* Ap = A + (size_t)row0 * K + k0;
            ra0 = *(const float4*)(Ap + (size_t)ar0 * K + akc);
            ra1 = *(const float4*)(Ap + (size_t)(ar0 + 64) * K + akc);
            const float* Bp = B + (size_t)k0 * N + col0;
            rb0 = *(const float4*)(Bp + (size_t)bk0 * N + bjc);
            rb1 = *(const float4*)(Bp + (size_t)(bk0 + 8) * N + bjc);
        }

#pragma unroll
        for (int k = 0; k < 16; k++) {
            float4 a0 = *(const float4*)&As[k][ty << 3];
            float4 a1 = *(const float4*)&As[k][(ty << 3) + 4];
            const ulonglong2* bp = (const ulonglong2*)&Bs[k][tx << 3];
            ulonglong2 b01 = bp[0];
            ulonglong2 b23 = bp[1];
            float av[8] = {a0.x, a0.y, a0.z, a0.w, a1.x, a1.y, a1.z, a1.w};
#pragma unroll
            for (int i = 0; i < 8; i++) {
                ull ap = pack_dup(av[i]);
                ffma2(acc[i][0], ap, b01.x);
                ffma2(acc[i][1], ap, b01.y);
                ffma2(acc[i][2], ap, b23.x);
                ffma2(acc[i][3], ap, b23.y);
            }
        }
        __syncthreads();
    }

    // epilogue
    float* Cp = C + (size_t)(row0 + (ty << 3)) * N + col0 + (tx << 3);
#pragma unroll
    for (int r = 0; r < 8; r++) {
        float o[8];
#pragma unroll
        for (int j = 0; j < 4; j++) unpack2(acc[r][j], o[2 * j], o[2 * j + 1]);
        *(float4*)(Cp + (size_t)r * N)     = make_float4(o[0], o[1], o[2], o[3]);
        *(float4*)(Cp + (size_t)r * N + 4) = make_float4(o[4], o[5], o[6], o[7]);
    }
}

// ---------------------------------------------------------------------------
// Gaussian banded smoothing along n, per head, row-normalized.
// grid: (NSEQ/TN, 2 channel-halves, BATCH*NHEAD), 256 threads.
// s[b,n,h*128+c] = (1/Z(n)) * sum_{j=0..64} ew[j] * y[b, n-WIN+j, h*128+c]
// ---------------------------------------------------------------------------
__global__ __launch_bounds__(256)
void smooth_kernel(const float* __restrict__ y, float* __restrict__ s,
                   const float* __restrict__ sigma) {
    __shared__ float yt[TN + 2 * WIN][64];   // 128 rows x 64 channels
    __shared__ float ew[2 * WIN + 1];
    __shared__ float invZ[TN];

    const int n0   = blockIdx.x * TN;
    const int half = blockIdx.y;
    const int bh   = blockIdx.z;
    const int b    = bh >> 3;            // / NHEAD
    const int h    = bh & 7;
    const int tid  = threadIdx.x;

    const float* ybase = y + (size_t)b * NSEQ * INNER + h * DHEAD + half * 64;

    // load 128 rows x 64 channels (16 float4 per row); zero out-of-range rows
    for (int i = tid; i < 128 * 16; i += 256) {
        const int r = i >> 4;
        const int c = (i & 15) << 2;
        const int m = n0 - WIN + r;
        float4 v = make_float4(0.f, 0.f, 0.f, 0.f);
        if (m >= 0 && m < NSEQ) v = *(const float4*)(ybase + (size_t)m * INNER + c);
        *(float4*)&yt[r][c] = v;
    }

    if (tid < 2 * WIN + 1) {
        const float sg = sigma[h];
        const float d  = (float)(tid - WIN);
        ew[tid] = __expf(-d * d / (2.f * sg * sg));
    }
    __syncthreads();

    if (tid < TN) {
        const int n = n0 + tid;
        float z = 0.f;
#pragma unroll
        for (int j = 0; j <= 2 * WIN; j++) {
            const int m = n - WIN + j;
            if (m >= 0 && m < NSEQ) z += ew[j];
        }
        invZ[tid] = 1.f / z;
    }
    __syncthreads();

    // compute: channel-pair per thread; 8 t-rows per thread
    const int cp = tid & 31;     // channel pair 0..31
    const int tg = tid >> 5;     // 0..7
#pragma unroll
    for (int k = 0; k < 8; k++) {
        const int t = tg * 8 + k;
        float ax = 0.f, ay = 0.f;
#pragma unroll
        for (int j = 0; j <= 2 * WIN; j++) {
            const float w = ew[j];
            const float2 v = *(const float2*)&yt[t + j][cp << 1];
            ax = fmaf(w, v.x, ax);
            ay = fmaf(w, v.y, ay);
        }
        const float iz = invZ[t];
        const int n = n0 + t;
        float2* outp = (float2*)(s + ((size_t)b * NSEQ + n) * INNER
                                 + h * DHEAD + half * 64 + (cp << 1));
        *outp = make_float2(ax * iz, ay * iz);
    }
}

// ---------------------------------------------------------------------------
extern "C" void kernel_launch(void* const* d_in, const int* in_sizes, int n_in,
                              void* d_out, int out_size) {
    const float* x     = (const float*)d_in[0];
    const float* Wg    = (const float*)d_in[1];
    const float* Wout  = (const float*)d_in[2];
    const float* sigma = (const float*)d_in[3];
    float* out = (float*)d_out;

    float* y = nullptr;
    float* s = nullptr;
    cudaGetSymbolAddress((void**)&y, g_y);
    cudaGetSymbolAddress((void**)&s, g_s);

    // GEMM1: y[8192,1024] = x[8192,512] @ Wg[512,1024]
    gemm128_f32x2<<<dim3(INNER / 128, MROWS / 128), 256>>>(x, Wg, y, MROWS, INNER, DIM);

    // Gaussian banded attention (row-normalized local smoothing per head)
    smooth_kernel<<<dim3(NSEQ / TN, 2, BATCH * NHEAD), 256>>>(y, s, sigma);

    // GEMM2: out[8192,512] = s[8192,1024] @ Wout[1024,512]
    gemm128_f32x2<<<dim3(DIM / 128, MROWS / 128), 256>>>(s, Wout, out, MROWS, DIM, INNER);
}